// round 1
// baseline (speedup 1.0000x reference)
#include <cuda_runtime.h>
#include <cooperative_groups.h>

namespace cg = cooperative_groups;

namespace {
constexpr int   kB       = 8;
constexpr int   kNT      = 256;
constexpr int   kNZ      = 256;
constexpr int   kNX      = 256;
constexpr int   kNREC    = 64;
constexpr int   kCluster = 8;                 // CTAs per batch (rows split)
constexpr int   kRows    = kNZ / kCluster;    // 32 rows per CTA
constexpr int   kThreads = 512;               // 2 groups of 256 (column = tid & 255)
constexpr float kDT2     = 1.0e-6f;           // DT*DT
constexpr float kInvDH2  = 0.01f;             // 1/(DH*DH)

constexpr int kBufFloats = kRows * kNX;       // 8192 floats = 32KB per buffer
constexpr int kWavOff    = 2 * kBufFloats;    // after the two ping-pong buffers
constexpr int kIntOff    = kWavOff + kNT;     // int section (rec lists) after wav
constexpr int kSmemBytes = (kIntOff + 64 + 64 + 4) * 4;  // ~67 KB
}

__global__ void __launch_bounds__(kThreads, 1)
wave_fd_kernel(const float* __restrict__ x,
               const float* __restrict__ vp,
               const int*   __restrict__ src_loc,
               const int*   __restrict__ rec_loc,
               float*       __restrict__ out)
{
    extern __shared__ float sm[];
    float* bufA   = sm;
    float* bufB   = sm + kBufFloats;
    float* wav    = sm + kWavOff;
    int*   recOff = (int*)(sm + kIntOff);
    int*   recK   = recOff + 64;
    int*   recCnt = recK + 64;

    cg::cluster_group cluster = cg::this_cluster();
    const int rank  = (int)cluster.block_rank();
    const int batch = blockIdx.x / kCluster;
    const int tid   = threadIdx.x;
    const int c     = tid & (kNX - 1);   // column 0..255
    const int g     = tid >> 8;          // 0 or 1: which 16-row half of the slab
    const int gz0   = rank * kRows + g * 16;   // first global row of this strip

    // ---- init: zero both ping-pong buffers, preload wavelet, build receiver list ----
    for (int i = tid; i < 2 * kBufFloats; i += kThreads) sm[i] = 0.0f;
    if (tid < kNT) wav[tid] = x[batch * kNT + tid];
    if (tid == 0) *recCnt = 0;
    __syncthreads();
    if (tid < kNREC) {
        int rz = rec_loc[(batch * kNREC + tid) * 2 + 0];
        int rx = rec_loc[(batch * kNREC + tid) * 2 + 1];
        if (rz >= rank * kRows && rz < (rank + 1) * kRows) {
            int slot = atomicAdd(recCnt, 1);
            recOff[slot] = (rz - rank * kRows) * kNX + rx;
            recK[slot]   = tid;
        }
    }
    __syncthreads();
    const int cnt = *recCnt;

    // ---- source ownership ----
    const int  sz     = src_loc[batch * 2 + 0];
    const int  sx     = src_loc[batch * 2 + 1];
    const bool isSrc  = (c == sx) && (sz >= gz0) && (sz < gz0 + 16);
    const int  srcOff = (sz - rank * kRows) * kNX + c;

    // ---- per-cell coefficients (vp^2*dt^2) and previous field h^{t-1} in registers ----
    float c2[16], h2[16];
#pragma unroll
    for (int i = 0; i < 16; i++) {
        float v = vp[(gz0 + i) * kNX + c];
        c2[i] = v * v * kDT2;
        h2[i] = 0.0f;
    }

    const bool active    = (c > 0) && (c < kNX - 1);       // boundary cols stay 0
    const bool skipFirst = (rank == 0) && (g == 0);        // global row 0 stays 0
    const bool skipLast  = (rank == kCluster - 1) && (g == 1); // global row 255 stays 0

    // ---- DSMEM neighbor pointers for halo rows (clamped at cluster edges) ----
    const int prevRank = (rank == 0) ? 0 : rank - 1;
    const int nextRank = (rank == kCluster - 1) ? rank : rank + 1;
    const float* prevA = cluster.map_shared_rank(bufA, prevRank);
    const float* prevB = cluster.map_shared_rank(bufB, prevRank);
    const float* nextA = cluster.map_shared_rank(bufA, nextRank);
    const float* nextB = cluster.map_shared_rank(bufB, nextRank);

    cluster.sync();   // buffers zeroed in all CTAs before any halo read

    const int strip = g * 16 * kNX + c;

    for (int t = 0; t < kNT; t++) {
        const float* cur     = (t & 1) ? bufB : bufA;
        float*       nxt     = (t & 1) ? bufA : bufB;
        const float* prevCur = (t & 1) ? prevB : prevA;
        const float* nextCur = (t & 1) ? nextB : nextA;

        if (active) {
            const float* cb = cur + strip;
            float*       nb = nxt + strip;

            // one DSMEM halo load per thread (row above for g=0, row below for g=1)
            float halo;
            if (g == 0) halo = prevCur[(kRows - 1) * kNX + c];
            else        halo = nextCur[c];

            float cm1 = (g == 0) ? halo : cb[-kNX];
            float c0  = cb[0];
#pragma unroll
            for (int i = 0; i < 16; i++) {
                float cp1;
                if (i < 15)      cp1 = cb[(i + 1) * kNX];
                else if (g == 0) cp1 = cb[16 * kNX];     // first row of the g=1 half
                else             cp1 = halo;             // next CTA's row 0
                float l   = cb[i * kNX - 1];
                float r   = cb[i * kNX + 1];
                float lap = ((cm1 + cp1) + (l + r) - 4.0f * c0) * kInvDH2;
                float hn  = fmaf(c2[i], lap, 2.0f * c0 - h2[i]);
                h2[i] = c0;
                bool store = true;
                if (i == 0  && skipFirst) store = false;  // global row 0
                if (i == 15 && skipLast)  store = false;  // global row 255
                if (store) nb[i * kNX] = hn;
                cm1 = c0; c0 = cp1;
            }
            // source injection: this thread is the one that wrote the src cell
            if (isSrc) nxt[srcOff] += kDT2 * wav[t];
        }
        __syncthreads();                 // nxt complete (incl. injection) within CTA
        if (tid < cnt)
            out[(batch * kNT + t) * kNREC + recK[tid]] = nxt[recOff[tid]];
        cluster.sync();                  // nxt complete cluster-wide before it becomes cur
    }
}

extern "C" void kernel_launch(void* const* d_in, const int* in_sizes, int n_in,
                              void* d_out, int out_size)
{
    (void)in_sizes; (void)n_in; (void)out_size;
    const float* x   = (const float*)d_in[0];
    const float* vp  = (const float*)d_in[1];
    const int*   src = (const int*)d_in[2];
    const int*   rec = (const int*)d_in[3];
    float*       out = (float*)d_out;

    cudaFuncSetAttribute(wave_fd_kernel,
                         cudaFuncAttributeMaxDynamicSharedMemorySize, kSmemBytes);

    cudaLaunchConfig_t cfg = {};
    cfg.gridDim          = dim3(kB * kCluster, 1, 1);   // 64 CTAs = 8 clusters of 8
    cfg.blockDim         = dim3(kThreads, 1, 1);
    cfg.dynamicSmemBytes = kSmemBytes;
    cfg.stream           = 0;

    cudaLaunchAttribute attr[1];
    attr[0].id = cudaLaunchAttributeClusterDimension;
    attr[0].val.clusterDim.x = kCluster;
    attr[0].val.clusterDim.y = 1;
    attr[0].val.clusterDim.z = 1;
    cfg.attrs    = attr;
    cfg.numAttrs = 1;

    cudaLaunchKernelEx(&cfg, wave_fd_kernel, x, vp, src, rec, out);
}

// round 2
// speedup vs baseline: 1.0897x; 1.0897x over previous
#include <cuda_runtime.h>
#include <cooperative_groups.h>

namespace cg = cooperative_groups;

namespace {
constexpr int   kB       = 8;
constexpr int   kNT      = 256;
constexpr int   kNZ      = 256;
constexpr int   kNX      = 256;
constexpr int   kNREC    = 64;
constexpr int   kThreads = 512;               // 2 groups of 256 (column = tid & 255)
constexpr float kDT2     = 1.0e-6f;           // DT*DT
constexpr float kInvDH2  = 0.01f;             // 1/(DH*DH)

constexpr int smem_bytes(int cluster) {
    int rows = kNZ / cluster;
    int bufFloats = rows * kNX;
    int intOff = 2 * bufFloats + kNT;
    return (intOff + 64 + 64 + 4) * 4;
}
}

template <int CLUSTER>
__global__ void __launch_bounds__(kThreads, 1)
wave_fd_kernel(const float* __restrict__ x,
               const float* __restrict__ vp,
               const int*   __restrict__ src_loc,
               const int*   __restrict__ rec_loc,
               float*       __restrict__ out)
{
    constexpr int kRows = kNZ / CLUSTER;      // rows per CTA
    constexpr int kHalf = kRows / 2;          // rows per thread
    constexpr int kBufFloats = kRows * kNX;
    constexpr int kWavOff = 2 * kBufFloats;
    constexpr int kIntOff = kWavOff + kNT;

    extern __shared__ float sm[];
    float* bufA   = sm;
    float* bufB   = sm + kBufFloats;
    float* wav    = sm + kWavOff;
    int*   recOff = (int*)(sm + kIntOff);
    int*   recK   = recOff + 64;
    int*   recCnt = recK + 64;

    cg::cluster_group cluster = cg::this_cluster();
    const int rank  = (int)cluster.block_rank();
    const int batch = blockIdx.x / CLUSTER;
    const int tid   = threadIdx.x;
    const int c     = tid & (kNX - 1);        // column 0..255
    const int g     = tid >> 8;               // which half of the slab
    const int gz0   = rank * kRows + g * kHalf;

    // ---- init: zero ping-pong buffers, preload wavelet, build receiver list ----
    for (int i = tid; i < 2 * kBufFloats; i += kThreads) sm[i] = 0.0f;
    if (tid < kNT) wav[tid] = x[batch * kNT + tid];
    if (tid == 0) *recCnt = 0;
    __syncthreads();
    if (tid < kNREC) {
        int rz = rec_loc[(batch * kNREC + tid) * 2 + 0];
        int rx = rec_loc[(batch * kNREC + tid) * 2 + 1];
        if (rz >= rank * kRows && rz < (rank + 1) * kRows) {
            int slot = atomicAdd(recCnt, 1);
            recOff[slot] = (rz - rank * kRows) * kNX + rx;
            recK[slot]   = tid;
        }
    }
    __syncthreads();
    const int cnt = *recCnt;

    // ---- source ownership ----
    const int  sz     = src_loc[batch * 2 + 0];
    const int  sx     = src_loc[batch * 2 + 1];
    const bool isSrc  = (c == sx) && (sz >= gz0) && (sz < gz0 + kHalf);
    const int  srcOff = (sz - rank * kRows) * kNX + c;

    // ---- per-cell coefficients and h^{t-1} in registers ----
    float c2[kHalf], h2[kHalf];
#pragma unroll
    for (int i = 0; i < kHalf; i++) {
        float v = vp[(gz0 + i) * kNX + c];
        c2[i] = v * v * kDT2;
        h2[i] = 0.0f;
    }

    const bool active    = (c > 0) && (c < kNX - 1);
    const bool skipFirst = (rank == 0) && (g == 0);            // global row 0
    const bool skipLast  = (rank == CLUSTER - 1) && (g == 1);  // global row NZ-1

    // ---- DSMEM neighbor pointers for halo rows (clamped at cluster edges) ----
    const int prevRank = (rank == 0) ? 0 : rank - 1;
    const int nextRank = (rank == CLUSTER - 1) ? rank : rank + 1;
    const float* prevA = cluster.map_shared_rank(bufA, prevRank);
    const float* prevB = cluster.map_shared_rank(bufB, prevRank);
    const float* nextA = cluster.map_shared_rank(bufA, nextRank);
    const float* nextB = cluster.map_shared_rank(bufB, nextRank);

    cluster.sync();   // buffers zeroed everywhere before first halo read

    const int strip = g * kHalf * kNX + c;

    for (int t = 0; t < kNT; t++) {
        const float* cur     = (t & 1) ? bufB : bufA;
        float*       nxt     = (t & 1) ? bufA : bufB;
        const float* prevCur = (t & 1) ? prevB : prevA;
        const float* nextCur = (t & 1) ? nextB : nextA;

        if (active) {
            const float* cb = cur + strip;
            float*       nb = nxt + strip;

            // one DSMEM halo load per thread
            float halo = (g == 0) ? prevCur[(kRows - 1) * kNX + c]
                                  : nextCur[c];

            float cm1 = (g == 0) ? halo : cb[-kNX];
            float c0  = cb[0];
#pragma unroll
            for (int i = 0; i < kHalf; i++) {
                float cp1;
                if (i < kHalf - 1)  cp1 = cb[(i + 1) * kNX];
                else if (g == 0)    cp1 = cb[kHalf * kNX];   // first row of g=1 half
                else                cp1 = halo;              // next CTA's row 0
                float l   = cb[i * kNX - 1];
                float r   = cb[i * kNX + 1];
                float lap = ((cm1 + cp1) + (l + r) - 4.0f * c0) * kInvDH2;
                float hn  = fmaf(c2[i], lap, 2.0f * c0 - h2[i]);
                h2[i] = c0;
                bool store = true;
                if (i == 0         && skipFirst) store = false;
                if (i == kHalf - 1 && skipLast)  store = false;
                if (store) nb[i * kNX] = hn;
                cm1 = c0; c0 = cp1;
            }
            if (isSrc) nxt[srcOff] += kDT2 * wav[t];
        }

        cluster.sync();   // single barrier per step: nxt complete cluster-wide

        // gather AFTER the sync; this buffer is not rewritten until t+2,
        // which is ordered after sync(t+1) > this gather.
        if (tid < cnt)
            out[(batch * kNT + t) * kNREC + recK[tid]] = nxt[recOff[tid]];
    }
}

extern "C" void kernel_launch(void* const* d_in, const int* in_sizes, int n_in,
                              void* d_out, int out_size)
{
    (void)in_sizes; (void)n_in; (void)out_size;
    const float* x   = (const float*)d_in[0];
    const float* vp  = (const float*)d_in[1];
    const int*   src = (const int*)d_in[2];
    const int*   rec = (const int*)d_in[3];
    float*       out = (float*)d_out;

    // ---- preferred: cluster of 16 (needs non-portable opt-in) ----
    cudaFuncSetAttribute(wave_fd_kernel<16>,
                         cudaFuncAttributeMaxDynamicSharedMemorySize, smem_bytes(16));
    cudaFuncSetAttribute(wave_fd_kernel<16>,
                         cudaFuncAttributeNonPortableClusterSizeAllowed, 1);
    cudaFuncSetAttribute(wave_fd_kernel<8>,
                         cudaFuncAttributeMaxDynamicSharedMemorySize, smem_bytes(8));

    // pure query (no stream op): how big a cluster will the driver accept?
    int maxCluster = 0;
    {
        cudaLaunchConfig_t probe = {};
        probe.gridDim          = dim3(kB * 16, 1, 1);
        probe.blockDim         = dim3(kThreads, 1, 1);
        probe.dynamicSmemBytes = smem_bytes(16);
        cudaOccupancyMaxPotentialClusterSize(&maxCluster, (const void*)wave_fd_kernel<16>, &probe);
    }

    cudaLaunchAttribute attr[1];
    attr[0].id = cudaLaunchAttributeClusterDimension;
    attr[0].val.clusterDim.y = 1;
    attr[0].val.clusterDim.z = 1;

    cudaLaunchConfig_t cfg = {};
    cfg.blockDim = dim3(kThreads, 1, 1);
    cfg.stream   = 0;
    cfg.attrs    = attr;
    cfg.numAttrs = 1;

    if (maxCluster >= 16) {
        cfg.gridDim              = dim3(kB * 16, 1, 1);
        cfg.dynamicSmemBytes     = smem_bytes(16);
        attr[0].val.clusterDim.x = 16;
        cudaLaunchKernelEx(&cfg, wave_fd_kernel<16>, x, vp, src, rec, out);
    } else {
        cfg.gridDim              = dim3(kB * 8, 1, 1);
        cfg.dynamicSmemBytes     = smem_bytes(8);
        attr[0].val.clusterDim.x = 8;
        cudaLaunchKernelEx(&cfg, wave_fd_kernel<8>, x, vp, src, rec, out);
    }
}